// round 4
// baseline (speedup 1.0000x reference)
#include <cuda_runtime.h>
#include <cstdint>

#define NH   12
#define DHD  64
#define NSEQ 1024
#define DM   768
#define NTB  16
#define NS   16384   // NTB * NSEQ tokens

// ---------------------------------------------------------------------------
// Scratch (static device globals; no runtime allocation allowed)
// ---------------------------------------------------------------------------
__device__ __align__(256) float g_q[(size_t)NTB * NH * NSEQ * DHD];   // tf32(0.125*q)
__device__ __align__(256) float g_k[(size_t)NTB * NH * NSEQ * DHD];   // tf32(k)
__device__ __align__(256) float g_v[(size_t)NTB * NH * NSEQ * DHD];   // tf32(v)
__device__ __align__(256) float g_ctx[(size_t)NS * DM];               // tf32(ctx)
__device__ __align__(256) float g_xc[(size_t)NS * DM];                // tf32(x)
__device__ __align__(256) float g_wqc[(size_t)DM * DM];
__device__ __align__(256) float g_wkc[(size_t)DM * DM];
__device__ __align__(256) float g_wvc[(size_t)DM * DM];
__device__ __align__(256) float g_woc[(size_t)DM * DM];

// ---------------------------------------------------------------------------
// Helpers
// ---------------------------------------------------------------------------
__device__ __forceinline__ float f2tf(float x) {
    unsigned u;
    asm("cvt.rna.tf32.f32 %0, %1;" : "=r"(u) : "f"(x));
    return __uint_as_float(u);
}

__device__ __forceinline__ uint32_t smem_u32(const void* p) {
    uint32_t a;
    asm("{ .reg .u64 t; cvta.to.shared.u64 t, %1; cvt.u32.u64 %0, t; }" : "=r"(a) : "l"(p));
    return a;
}

__device__ __forceinline__ void cp16(uint32_t dst, const void* src) {
    asm volatile("cp.async.cg.shared.global [%0], [%1], 16;" :: "r"(dst), "l"(src) : "memory");
}
#define CP_COMMIT() asm volatile("cp.async.commit_group;" ::: "memory")
#define CP_WAIT(n)  asm volatile("cp.async.wait_group %0;" :: "n"(n) : "memory")

__device__ __forceinline__ void mma8(float& c0, float& c1, float& c2, float& c3,
                                     unsigned a0, unsigned a1, unsigned a2, unsigned a3,
                                     unsigned b0, unsigned b1) {
    asm volatile(
        "mma.sync.aligned.m16n8k8.row.col.f32.tf32.tf32.f32 "
        "{%0,%1,%2,%3},{%4,%5,%6,%7},{%8,%9},{%0,%1,%2,%3};"
        : "+f"(c0), "+f"(c1), "+f"(c2), "+f"(c3)
        : "r"(a0), "r"(a1), "r"(a2), "r"(a3), "r"(b0), "r"(b1));
}

// ---------------------------------------------------------------------------
// tf32 pre-round (elementwise). which: 0=x,1=Wq,2=Wk,3=Wv,4=Wo
// ---------------------------------------------------------------------------
__global__ __launch_bounds__(256) void cvt_k(const float* __restrict__ s, int which, int n4) {
    float* dsel = (which == 0) ? g_xc : (which == 1) ? g_wqc : (which == 2) ? g_wkc
                : (which == 3) ? g_wvc : g_woc;
    int i = blockIdx.x * blockDim.x + threadIdx.x;
    if (i < n4) {
        float4 v = reinterpret_cast<const float4*>(s)[i];
        v.x = f2tf(v.x); v.y = f2tf(v.y); v.z = f2tf(v.z); v.w = f2tf(v.w);
        reinterpret_cast<float4*>(dsel)[i] = v;
    }
}

// ---------------------------------------------------------------------------
// HMMA tf32 GEMM: out[s,c] = sum_k A[s,k]*W[c,k] + bias[c]
// CTA 128x128, BK=32, 2-stage cp.async pipeline. 256 thr (8 warps 4m x 2n).
// Stage layout: [stage][ A 128x36 | B 128x36 ]  (stride 36 -> conflict-free,
// 144 B row pitch is 16B-aligned for cp.async).
// mode: 0 = head-split q (scale 0.125 + tf32 round)
//       1 = head-split k/v (tf32 round)
//       2 = flat raw
// ---------------------------------------------------------------------------
#define GSTG 4608                 // floats per array (128*36)
#define GSMEM_F (2 * 2 * GSTG)    // 18432 floats = 73728 B

__device__ __forceinline__ void gemm_body(const float* __restrict__ A,
                                          const float* __restrict__ W,
                                          const float* __restrict__ bias,
                                          float* __restrict__ dst, int mode) {
    extern __shared__ float sm[];
    const uint32_t smb = smem_u32(sm);
    const int tid  = threadIdx.x;
    const int lane = tid & 31, wid = tid >> 5;
    const int wm = (wid & 3) * 32;
    const int wn = (wid >> 2) * 64;
    const int row0 = blockIdx.x * 128, col0 = blockIdx.y * 128;
    const int lr = lane >> 2, lc = lane & 3;

    float acc[2][8][4];
#pragma unroll
    for (int i = 0; i < 2; i++)
#pragma unroll
        for (int j = 0; j < 8; j++)
#pragma unroll
            for (int e = 0; e < 4; e++) acc[i][j][e] = 0.f;

    // ---- prefetch helper: 1024 16B-chunks per matrix, 256 threads -> 4 each
    auto prefetch = [&](int s, int kk) {
        const uint32_t ab = smb + (uint32_t)(s * 2 * GSTG) * 4u;
        const uint32_t bb = ab + (uint32_t)GSTG * 4u;
#pragma unroll
        for (int u = tid; u < 1024; u += 256) {
            const int row = u >> 3, c = (u & 7) << 2;
            cp16(ab + (uint32_t)(row * 36 + c) * 4u,
                 A + (size_t)(row0 + row) * DM + kk + c);
        }
#pragma unroll
        for (int u = tid; u < 1024; u += 256) {
            const int row = u >> 3, c = (u & 7) << 2;
            cp16(bb + (uint32_t)(row * 36 + c) * 4u,
                 W + (size_t)(col0 + row) * DM + kk + c);
        }
    };

    prefetch(0, 0);
    CP_COMMIT();

    for (int it = 0; it < DM / 32; it++) {
        const int s = it & 1;
        if (it + 1 < DM / 32) {
            prefetch(s ^ 1, (it + 1) * 32);
            CP_COMMIT();
            CP_WAIT(1);
        } else {
            CP_WAIT(0);
        }
        __syncthreads();

        const float* Asp = sm + s * 2 * GSTG;
        const float* Bsp = Asp + GSTG;
#pragma unroll
        for (int ks = 0; ks < 4; ks++) {
            const int k0 = ks * 8;
            unsigned af[2][4];
#pragma unroll
            for (int mi = 0; mi < 2; mi++) {
                const int r = wm + mi * 16 + lr;
                af[mi][0] = __float_as_uint(Asp[r * 36 + k0 + lc]);
                af[mi][1] = __float_as_uint(Asp[(r + 8) * 36 + k0 + lc]);
                af[mi][2] = __float_as_uint(Asp[r * 36 + k0 + 4 + lc]);
                af[mi][3] = __float_as_uint(Asp[(r + 8) * 36 + k0 + 4 + lc]);
            }
            unsigned bf[8][2];
#pragma unroll
            for (int ni = 0; ni < 8; ni++) {
                const int r = wn + ni * 8 + lr;
                bf[ni][0] = __float_as_uint(Bsp[r * 36 + k0 + lc]);
                bf[ni][1] = __float_as_uint(Bsp[r * 36 + k0 + 4 + lc]);
            }
#pragma unroll
            for (int mi = 0; mi < 2; mi++)
#pragma unroll
                for (int ni = 0; ni < 8; ni++)
                    mma8(acc[mi][ni][0], acc[mi][ni][1], acc[mi][ni][2], acc[mi][ni][3],
                         af[mi][0], af[mi][1], af[mi][2], af[mi][3],
                         bf[ni][0], bf[ni][1]);
        }
        __syncthreads();
    }

    // epilogue
#pragma unroll
    for (int mi = 0; mi < 2; mi++)
#pragma unroll
        for (int ni = 0; ni < 8; ni++)
#pragma unroll
            for (int e = 0; e < 4; e++) {
                const int gr = row0 + wm + mi * 16 + lr + ((e >> 1) << 3);
                const int gc = col0 + wn + ni * 8 + (lc << 1) + (e & 1);
                float v = acc[mi][ni][e] + __ldg(bias + gc);
                if (mode == 0) v = f2tf(v * 0.125f);
                else if (mode == 1) v = f2tf(v);
                if (mode <= 1) {
                    const int tb = gr >> 10, n = gr & 1023;
                    const int h = gc >> 6, d = gc & 63;
                    dst[(((size_t)(tb * NH + h)) * NSEQ + n) * DHD + d] = v;
                } else {
                    dst[(size_t)gr * DM + gc] = v;
                }
            }
}

__global__ __launch_bounds__(256, 2) void gemm_qkv_k(const float* __restrict__ bq,
                                                     const float* __restrict__ bk,
                                                     const float* __restrict__ bv) {
    const int z = blockIdx.z;
    const float* W = (z == 0) ? g_wqc : (z == 1) ? g_wkc : g_wvc;
    const float* b = (z == 0) ? bq : (z == 1) ? bk : bv;
    float* dst = (z == 0) ? g_q : (z == 1) ? g_k : g_v;
    gemm_body(g_xc, W, b, dst, (z == 0) ? 0 : 1);
}

__global__ __launch_bounds__(256, 2) void gemm_out_k(const float* __restrict__ bo,
                                                     float* __restrict__ out) {
    gemm_body(g_ctx, g_woc, bo, out, 2);
}

// ---------------------------------------------------------------------------
// Attention: per (tb,h), 1024x1024x64. CTA = 128 q-rows, streams 32-key blocks
// through a 2-stage cp.async pipeline. Inputs pre-rounded (q also pre-scaled).
// P = relu(q_s k^T); ctx = (P @ v) / (rowsum(P) + eps).
// ---------------------------------------------------------------------------
#define QS_STR 68
#define KS_STR 68
#define VS_STR 72   // 72 % 32 == 8 -> conflict-free V B-frag loads
#define PS_STR 36
#define AQ_F   (128 * QS_STR)            // 8704
#define AK_F   (32 * KS_STR)             // 2176
#define AV_F   (32 * VS_STR)             // 2304
#define AP_F   (4 * 32 * PS_STR)         // 4608
#define ATT_SMEM_F (AQ_F + 2 * (AK_F + AV_F) + AP_F)   // 22272 floats = 89088 B

__global__ __launch_bounds__(128, 2) void attn_k() {
    extern __shared__ float sm[];
    float* Qs  = sm;
    float* Ks0 = Qs + AQ_F;                  // [2][32][68]
    float* Vs0 = Ks0 + 2 * AK_F;             // [2][32][72]
    float* Ps  = Vs0 + 2 * AV_F;             // [4][32][36]
    const uint32_t smb = smem_u32(sm);

    const int tid = threadIdx.x, lane = tid & 31, wid = tid >> 5;
    const int lr = lane >> 2, lc = lane & 3;
    const int qb = blockIdx.x, tbh = blockIdx.y;
    const float* qp = g_q + (size_t)tbh * NSEQ * DHD + (size_t)qb * 128 * DHD;
    const float* kp = g_k + (size_t)tbh * NSEQ * DHD;
    const float* vp = g_v + (size_t)tbh * NSEQ * DHD;

    // prefetch KV stage: 512 chunks K + 512 chunks V, 128 threads -> 4+4 each
    auto prefetch_kv = [&](int s, int kvb) {
        const uint32_t kb = smb + (uint32_t)(AQ_F + s * AK_F) * 4u;
        const uint32_t vb = smb + (uint32_t)(AQ_F + 2 * AK_F + s * AV_F) * 4u;
        const float* kg = kp + (size_t)kvb * 32 * DHD;
        const float* vg = vp + (size_t)kvb * 32 * DHD;
#pragma unroll
        for (int u = tid; u < 512; u += 128) {
            const int row = u >> 4, c = (u & 15) << 2;
            cp16(kb + (uint32_t)(row * KS_STR + c) * 4u, kg + row * DHD + c);
        }
#pragma unroll
        for (int u = tid; u < 512; u += 128) {
            const int row = u >> 4, c = (u & 15) << 2;
            cp16(vb + (uint32_t)(row * VS_STR + c) * 4u, vg + row * DHD + c);
        }
    };

    // Q load (once) + first KV stage, one commit group
#pragma unroll
    for (int u = tid; u < 2048; u += 128) {
        const int row = u >> 4, c = (u & 15) << 2;
        cp16(smb + (uint32_t)(row * QS_STR + c) * 4u, qp + row * DHD + c);
    }
    prefetch_kv(0, 0);
    CP_COMMIT();

    float ctx[2][8][4];
#pragma unroll
    for (int i = 0; i < 2; i++)
#pragma unroll
        for (int j = 0; j < 8; j++)
#pragma unroll
            for (int e = 0; e < 4; e++) ctx[i][j][e] = 0.f;
    float rs[2][2] = {{0.f, 0.f}, {0.f, 0.f}};

    const int wm = wid * 32;
    float* Pw = Ps + wid * 32 * PS_STR;

    for (int kvb = 0; kvb < NSEQ / 32; kvb++) {
        const int s = kvb & 1;
        if (kvb + 1 < NSEQ / 32) {
            prefetch_kv(s ^ 1, kvb + 1);
            CP_COMMIT();
            CP_WAIT(1);
        } else {
            CP_WAIT(0);
        }
        __syncthreads();

        const float* Ksp = Ks0 + s * AK_F;
        const float* Vsp = Vs0 + s * AV_F;

        // S = q_s @ k^T (warp: 32 q-rows x 32 keys)
        float sacc[2][4][4];
#pragma unroll
        for (int i = 0; i < 2; i++)
#pragma unroll
            for (int j = 0; j < 4; j++)
#pragma unroll
                for (int e = 0; e < 4; e++) sacc[i][j][e] = 0.f;

#pragma unroll
        for (int ks = 0; ks < 8; ks++) {
            const int k0 = ks * 8;
            unsigned af[2][4];
#pragma unroll
            for (int mi = 0; mi < 2; mi++) {
                const int r = wm + mi * 16 + lr;
                af[mi][0] = __float_as_uint(Qs[r * QS_STR + k0 + lc]);
                af[mi][1] = __float_as_uint(Qs[(r + 8) * QS_STR + k0 + lc]);
                af[mi][2] = __float_as_uint(Qs[r * QS_STR + k0 + 4 + lc]);
                af[mi][3] = __float_as_uint(Qs[(r + 8) * QS_STR + k0 + 4 + lc]);
            }
            unsigned bf[4][2];
#pragma unroll
            for (int ni = 0; ni < 4; ni++) {
                const int r = ni * 8 + lr;
                bf[ni][0] = __float_as_uint(Ksp[r * KS_STR + k0 + lc]);
                bf[ni][1] = __float_as_uint(Ksp[r * KS_STR + k0 + 4 + lc]);
            }
#pragma unroll
            for (int mi = 0; mi < 2; mi++)
#pragma unroll
                for (int ni = 0; ni < 4; ni++)
                    mma8(sacc[mi][ni][0], sacc[mi][ni][1], sacc[mi][ni][2], sacc[mi][ni][3],
                         af[mi][0], af[mi][1], af[mi][2], af[mi][3],
                         bf[ni][0], bf[ni][1]);
        }

        // relu + rowsum + stage P (per-warp region)
#pragma unroll
        for (int mi = 0; mi < 2; mi++)
#pragma unroll
            for (int ni = 0; ni < 4; ni++) {
                float p0 = fmaxf(sacc[mi][ni][0], 0.f);
                float p1 = fmaxf(sacc[mi][ni][1], 0.f);
                float p2 = fmaxf(sacc[mi][ni][2], 0.f);
                float p3 = fmaxf(sacc[mi][ni][3], 0.f);
                rs[mi][0] += p0 + p1;
                rs[mi][1] += p2 + p3;
                const int rb = mi * 16 + lr;
                const int cb = ni * 8 + (lc << 1);
                *reinterpret_cast<float2*>(Pw + rb * PS_STR + cb)       = make_float2(f2tf(p0), f2tf(p1));
                *reinterpret_cast<float2*>(Pw + (rb + 8) * PS_STR + cb) = make_float2(f2tf(p2), f2tf(p3));
            }
        __syncwarp();

        // ctx += P @ V
#pragma unroll
        for (int ks = 0; ks < 4; ks++) {
            const int k0 = ks * 8;
            unsigned af[2][4];
#pragma unroll
            for (int mi = 0; mi < 2; mi++) {
                const int r = mi * 16 + lr;
                af[mi][0] = __float_as_uint(Pw[r * PS_STR + k0 + lc]);
                af[mi][1] = __float_as_uint(Pw[(r + 8) * PS_STR + k0 + lc]);
                af[mi][2] = __float_as_uint(Pw[r * PS_STR + k0 + 4 + lc]);
                af[mi][3] = __float_as_uint(Pw[(r + 8) * PS_STR + k0 + 4 + lc]);
            }
            unsigned bf[8][2];
#pragma unroll
            for (int ni = 0; ni < 8; ni++) {
                bf[ni][0] = __float_as_uint(Vsp[(k0 + lc) * VS_STR + ni * 8 + lr]);
                bf[ni][1] = __float_as_uint(Vsp[(k0 + 4 + lc) * VS_STR + ni * 8 + lr]);
            }
#pragma unroll
            for (int mi = 0; mi < 2; mi++)
#pragma unroll
                for (int ni = 0; ni < 8; ni++)
                    mma8(ctx[mi][ni][0], ctx[mi][ni][1], ctx[mi][ni][2], ctx[mi][ni][3],
                         af[mi][0], af[mi][1], af[mi][2], af[mi][3],
                         bf[ni][0], bf[ni][1]);
        }
        __syncthreads();
    }

    // finalize rowsums
    float inv[2][2];
#pragma unroll
    for (int mi = 0; mi < 2; mi++)
#pragma unroll
        for (int hh = 0; hh < 2; hh++) {
            float r = rs[mi][hh];
            r += __shfl_xor_sync(0xffffffffu, r, 1);
            r += __shfl_xor_sync(0xffffffffu, r, 2);
            inv[mi][hh] = 1.f / (r + 1e-6f);
        }

    // write merged ctx [s, h*64 + d] (tf32-rounded: feeds out-proj GEMM)
    const int tb = tbh / NH, h = tbh % NH;
#pragma unroll
    for (int mi = 0; mi < 2; mi++)
#pragma unroll
        for (int ni = 0; ni < 8; ni++)
#pragma unroll
            for (int e = 0; e < 4; e++) {
                const int qrow = qb * 128 + wm + mi * 16 + lr + ((e >> 1) << 3);
                const int s = tb * NSEQ + qrow;
                const int c = h * DHD + ni * 8 + (lc << 1) + (e & 1);
                g_ctx[(size_t)s * DM + c] = f2tf(ctx[mi][ni][e] * inv[mi][e >> 1]);
            }
}

// ---------------------------------------------------------------------------
// Launch
// ---------------------------------------------------------------------------
extern "C" void kernel_launch(void* const* d_in, const int* in_sizes, int n_in,
                              void* d_out, int out_size) {
    const float* x  = (const float*)d_in[0];
    const float* Wq = (const float*)d_in[1];
    const float* bq = (const float*)d_in[2];
    const float* Wk = (const float*)d_in[3];
    const float* bk = (const float*)d_in[4];
    const float* Wv = (const float*)d_in[5];
    const float* bv = (const float*)d_in[6];
    const float* Wo = (const float*)d_in[7];
    const float* bo = (const float*)d_in[8];
    float* out = (float*)d_out;

    (void)in_sizes; (void)n_in; (void)out_size;

    cudaFuncSetAttribute(gemm_qkv_k, cudaFuncAttributeMaxDynamicSharedMemorySize,
                         (int)(GSMEM_F * sizeof(float)));
    cudaFuncSetAttribute(gemm_out_k, cudaFuncAttributeMaxDynamicSharedMemorySize,
                         (int)(GSMEM_F * sizeof(float)));
    cudaFuncSetAttribute(attn_k, cudaFuncAttributeMaxDynamicSharedMemorySize,
                         (int)(ATT_SMEM_F * sizeof(float)));

    // tf32 pre-round
    const int nx4 = (NS * DM) / 4, nw4 = (DM * DM) / 4;
    cvt_k<<<(nx4 + 255) / 256, 256>>>(x, 0, nx4);
    cvt_k<<<(nw4 + 255) / 256, 256>>>(Wq, 1, nw4);
    cvt_k<<<(nw4 + 255) / 256, 256>>>(Wk, 2, nw4);
    cvt_k<<<(nw4 + 255) / 256, 256>>>(Wv, 3, nw4);
    cvt_k<<<(nw4 + 255) / 256, 256>>>(Wo, 4, nw4);

    // q/k/v projections
    gemm_qkv_k<<<dim3(NS / 128, DM / 128, 3), 256, GSMEM_F * sizeof(float)>>>(bq, bk, bv);

    // spike attention
    attn_k<<<dim3(NSEQ / 128, NTB * NH), 128, ATT_SMEM_F * sizeof(float)>>>();

    // output projection
    gemm_out_k<<<dim3(NS / 128, DM / 128), 256, GSMEM_F * sizeof(float)>>>(bo, out);
}

// round 5
// speedup vs baseline: 1.5228x; 1.5228x over previous
#include <cuda_runtime.h>
#include <cstdint>

#define NH   12
#define DHD  64
#define NSEQ 1024
#define DM   768
#define NTB  16
#define NS   16384   // NTB * NSEQ tokens

// ---------------------------------------------------------------------------
// Scratch (static device globals; no runtime allocation allowed)
// ---------------------------------------------------------------------------
__device__ __align__(256) float g_q[(size_t)NTB * NH * NSEQ * DHD];   // tf32(0.125*q)
__device__ __align__(256) float g_k[(size_t)NTB * NH * NSEQ * DHD];   // tf32(k)
__device__ __align__(256) float g_v[(size_t)NTB * NH * NSEQ * DHD];   // tf32(v)
__device__ __align__(256) float g_ctx[(size_t)NS * DM];               // tf32(ctx)
__device__ __align__(256) float g_xc[(size_t)NS * DM];                // tf32(x)
__device__ __align__(256) float g_wqc[(size_t)DM * DM];
__device__ __align__(256) float g_wkc[(size_t)DM * DM];
__device__ __align__(256) float g_wvc[(size_t)DM * DM];
__device__ __align__(256) float g_woc[(size_t)DM * DM];

// ---------------------------------------------------------------------------
// Helpers
// ---------------------------------------------------------------------------
__device__ __forceinline__ float f2tf(float x) {
    unsigned u;
    asm("cvt.rna.tf32.f32 %0, %1;" : "=r"(u) : "f"(x));
    return __uint_as_float(u);
}

__device__ __forceinline__ uint32_t smem_u32(const void* p) {
    uint32_t a;
    asm("{ .reg .u64 t; cvta.to.shared.u64 t, %1; cvt.u32.u64 %0, t; }" : "=r"(a) : "l"(p));
    return a;
}

__device__ __forceinline__ void cp16(uint32_t dst, const void* src) {
    asm volatile("cp.async.cg.shared.global [%0], [%1], 16;" :: "r"(dst), "l"(src) : "memory");
}
#define CP_COMMIT() asm volatile("cp.async.commit_group;" ::: "memory")
#define CP_WAIT(n)  asm volatile("cp.async.wait_group %0;" :: "n"(n) : "memory")

__device__ __forceinline__ void mma8(float& c0, float& c1, float& c2, float& c3,
                                     unsigned a0, unsigned a1, unsigned a2, unsigned a3,
                                     unsigned b0, unsigned b1) {
    asm volatile(
        "mma.sync.aligned.m16n8k8.row.col.f32.tf32.tf32.f32 "
        "{%0,%1,%2,%3},{%4,%5,%6,%7},{%8,%9},{%0,%1,%2,%3};"
        : "+f"(c0), "+f"(c1), "+f"(c2), "+f"(c3)
        : "r"(a0), "r"(a1), "r"(a2), "r"(a3), "r"(b0), "r"(b1));
}

// ---------------------------------------------------------------------------
// tf32 pre-round (elementwise). which: 0=x,1=Wq,2=Wk,3=Wv,4=Wo
// ---------------------------------------------------------------------------
__global__ __launch_bounds__(256) void cvt_k(const float* __restrict__ s, int which, int n4) {
    float* dsel = (which == 0) ? g_xc : (which == 1) ? g_wqc : (which == 2) ? g_wkc
                : (which == 3) ? g_wvc : g_woc;
    int i = blockIdx.x * blockDim.x + threadIdx.x;
    if (i < n4) {
        float4 v = reinterpret_cast<const float4*>(s)[i];
        v.x = f2tf(v.x); v.y = f2tf(v.y); v.z = f2tf(v.z); v.w = f2tf(v.w);
        reinterpret_cast<float4*>(dsel)[i] = v;
    }
}

// ---------------------------------------------------------------------------
// HMMA tf32 GEMM: out[s,c] = sum_k A[s,k]*W[c,k] + bias[c]
// CTA 128x128, BK=32, 2-stage cp.async pipeline. 256 thr (8 warps 4m x 2n).
// NO min-blocks clause: R4 showed __launch_bounds__(256,2) caps regs at 128
// and spills the accumulators (R1 measured 138 regs for this structure).
// mode: 0 = head-split q (scale 0.125 + tf32 round)
//       1 = head-split k/v (tf32 round)
//       2 = flat raw
// ---------------------------------------------------------------------------
#define GSTG 4608                 // floats per array (128*36)
#define GSMEM_F (2 * 2 * GSTG)    // 18432 floats = 73728 B

__device__ __forceinline__ void gemm_body(const float* __restrict__ A,
                                          const float* __restrict__ W,
                                          const float* __restrict__ bias,
                                          float* __restrict__ dst, int mode) {
    extern __shared__ float sm[];
    const uint32_t smb = smem_u32(sm);
    const int tid  = threadIdx.x;
    const int lane = tid & 31, wid = tid >> 5;
    const int wm = (wid & 3) * 32;
    const int wn = (wid >> 2) * 64;
    const int row0 = blockIdx.x * 128, col0 = blockIdx.y * 128;
    const int lr = lane >> 2, lc = lane & 3;

    float acc[2][8][4];
#pragma unroll
    for (int i = 0; i < 2; i++)
#pragma unroll
        for (int j = 0; j < 8; j++)
#pragma unroll
            for (int e = 0; e < 4; e++) acc[i][j][e] = 0.f;

    // ---- prefetch helper: 1024 16B-chunks per matrix, 256 threads -> 4 each
    auto prefetch = [&](int s, int kk) {
        const uint32_t ab = smb + (uint32_t)(s * 2 * GSTG) * 4u;
        const uint32_t bb = ab + (uint32_t)GSTG * 4u;
#pragma unroll
        for (int u = tid; u < 1024; u += 256) {
            const int row = u >> 3, c = (u & 7) << 2;
            cp16(ab + (uint32_t)(row * 36 + c) * 4u,
                 A + (size_t)(row0 + row) * DM + kk + c);
        }
#pragma unroll
        for (int u = tid; u < 1024; u += 256) {
            const int row = u >> 3, c = (u & 7) << 2;
            cp16(bb + (uint32_t)(row * 36 + c) * 4u,
                 W + (size_t)(col0 + row) * DM + kk + c);
        }
    };

    prefetch(0, 0);
    CP_COMMIT();

    for (int it = 0; it < DM / 32; it++) {
        const int s = it & 1;
        if (it + 1 < DM / 32) {
            prefetch(s ^ 1, (it + 1) * 32);
            CP_COMMIT();
            CP_WAIT(1);
        } else {
            CP_WAIT(0);
        }
        __syncthreads();

        const float* Asp = sm + s * 2 * GSTG;
        const float* Bsp = Asp + GSTG;
#pragma unroll
        for (int ks = 0; ks < 4; ks++) {
            const int k0 = ks * 8;
            unsigned af[2][4];
#pragma unroll
            for (int mi = 0; mi < 2; mi++) {
                const int r = wm + mi * 16 + lr;
                af[mi][0] = __float_as_uint(Asp[r * 36 + k0 + lc]);
                af[mi][1] = __float_as_uint(Asp[(r + 8) * 36 + k0 + lc]);
                af[mi][2] = __float_as_uint(Asp[r * 36 + k0 + 4 + lc]);
                af[mi][3] = __float_as_uint(Asp[(r + 8) * 36 + k0 + 4 + lc]);
            }
            unsigned bf[8][2];
#pragma unroll
            for (int ni = 0; ni < 8; ni++) {
                const int r = wn + ni * 8 + lr;
                bf[ni][0] = __float_as_uint(Bsp[r * 36 + k0 + lc]);
                bf[ni][1] = __float_as_uint(Bsp[r * 36 + k0 + 4 + lc]);
            }
#pragma unroll
            for (int mi = 0; mi < 2; mi++)
#pragma unroll
                for (int ni = 0; ni < 8; ni++)
                    mma8(acc[mi][ni][0], acc[mi][ni][1], acc[mi][ni][2], acc[mi][ni][3],
                         af[mi][0], af[mi][1], af[mi][2], af[mi][3],
                         bf[ni][0], bf[ni][1]);
        }
        __syncthreads();
    }

    // epilogue
#pragma unroll
    for (int mi = 0; mi < 2; mi++)
#pragma unroll
        for (int ni = 0; ni < 8; ni++)
#pragma unroll
            for (int e = 0; e < 4; e++) {
                const int gr = row0 + wm + mi * 16 + lr + ((e >> 1) << 3);
                const int gc = col0 + wn + ni * 8 + (lc << 1) + (e & 1);
                float v = acc[mi][ni][e] + __ldg(bias + gc);
                if (mode == 0) v = f2tf(v * 0.125f);
                else if (mode == 1) v = f2tf(v);
                if (mode <= 1) {
                    const int tb = gr >> 10, n = gr & 1023;
                    const int h = gc >> 6, d = gc & 63;
                    dst[(((size_t)(tb * NH + h)) * NSEQ + n) * DHD + d] = v;
                } else {
                    dst[(size_t)gr * DM + gc] = v;
                }
            }
}

__global__ __launch_bounds__(256) void gemm_qkv_k(const float* __restrict__ bq,
                                                  const float* __restrict__ bk,
                                                  const float* __restrict__ bv) {
    const int z = blockIdx.z;
    const float* W = (z == 0) ? g_wqc : (z == 1) ? g_wkc : g_wvc;
    const float* b = (z == 0) ? bq : (z == 1) ? bk : bv;
    float* dst = (z == 0) ? g_q : (z == 1) ? g_k : g_v;
    gemm_body(g_xc, W, b, dst, (z == 0) ? 0 : 1);
}

__global__ __launch_bounds__(256) void gemm_out_k(const float* __restrict__ bo,
                                                  float* __restrict__ out) {
    gemm_body(g_ctx, g_woc, bo, out, 2);
}

// ---------------------------------------------------------------------------
// Attention: per (tb,h), 1024x1024x64. CTA = 128 q-rows, streams 32-key blocks
// through a 2-stage cp.async pipeline. Inputs pre-rounded (q also pre-scaled).
// P = relu(q_s k^T); ctx = (P @ v) / (rowsum(P) + eps).
// ---------------------------------------------------------------------------
#define QS_STR 68
#define KS_STR 68
#define VS_STR 72   // 72 % 32 == 8 -> conflict-free V B-frag loads
#define PS_STR 36
#define AQ_F   (128 * QS_STR)            // 8704
#define AK_F   (32 * KS_STR)             // 2176
#define AV_F   (32 * VS_STR)             // 2304
#define AP_F   (4 * 32 * PS_STR)         // 4608
#define ATT_SMEM_F (AQ_F + 2 * (AK_F + AV_F) + AP_F)   // 22272 floats = 89088 B

__global__ __launch_bounds__(128, 2) void attn_k() {
    extern __shared__ float sm[];
    float* Qs  = sm;
    float* Ks0 = Qs + AQ_F;                  // [2][32][68]
    float* Vs0 = Ks0 + 2 * AK_F;             // [2][32][72]
    float* Ps  = Vs0 + 2 * AV_F;             // [4][32][36]
    const uint32_t smb = smem_u32(sm);

    const int tid = threadIdx.x, lane = tid & 31, wid = tid >> 5;
    const int lr = lane >> 2, lc = lane & 3;
    const int qb = blockIdx.x, tbh = blockIdx.y;
    const float* qp = g_q + (size_t)tbh * NSEQ * DHD + (size_t)qb * 128 * DHD;
    const float* kp = g_k + (size_t)tbh * NSEQ * DHD;
    const float* vp = g_v + (size_t)tbh * NSEQ * DHD;

    // prefetch KV stage: 512 chunks K + 512 chunks V, 128 threads -> 4+4 each
    auto prefetch_kv = [&](int s, int kvb) {
        const uint32_t kb = smb + (uint32_t)(AQ_F + s * AK_F) * 4u;
        const uint32_t vb = smb + (uint32_t)(AQ_F + 2 * AK_F + s * AV_F) * 4u;
        const float* kg = kp + (size_t)kvb * 32 * DHD;
        const float* vg = vp + (size_t)kvb * 32 * DHD;
#pragma unroll
        for (int u = tid; u < 512; u += 128) {
            const int row = u >> 4, c = (u & 15) << 2;
            cp16(kb + (uint32_t)(row * KS_STR + c) * 4u, kg + row * DHD + c);
        }
#pragma unroll
        for (int u = tid; u < 512; u += 128) {
            const int row = u >> 4, c = (u & 15) << 2;
            cp16(vb + (uint32_t)(row * VS_STR + c) * 4u, vg + row * DHD + c);
        }
    };

    // Q load (once) + first KV stage, one commit group
#pragma unroll
    for (int u = tid; u < 2048; u += 128) {
        const int row = u >> 4, c = (u & 15) << 2;
        cp16(smb + (uint32_t)(row * QS_STR + c) * 4u, qp + row * DHD + c);
    }
    prefetch_kv(0, 0);
    CP_COMMIT();

    float ctx[2][8][4];
#pragma unroll
    for (int i = 0; i < 2; i++)
#pragma unroll
        for (int j = 0; j < 8; j++)
#pragma unroll
            for (int e = 0; e < 4; e++) ctx[i][j][e] = 0.f;
    float rs[2][2] = {{0.f, 0.f}, {0.f, 0.f}};

    const int wm = wid * 32;
    float* Pw = Ps + wid * 32 * PS_STR;

    for (int kvb = 0; kvb < NSEQ / 32; kvb++) {
        const int s = kvb & 1;
        if (kvb + 1 < NSEQ / 32) {
            prefetch_kv(s ^ 1, kvb + 1);
            CP_COMMIT();
            CP_WAIT(1);
        } else {
            CP_WAIT(0);
        }
        __syncthreads();

        const float* Ksp = Ks0 + s * AK_F;
        const float* Vsp = Vs0 + s * AV_F;

        // S = q_s @ k^T (warp: 32 q-rows x 32 keys)
        float sacc[2][4][4];
#pragma unroll
        for (int i = 0; i < 2; i++)
#pragma unroll
            for (int j = 0; j < 4; j++)
#pragma unroll
                for (int e = 0; e < 4; e++) sacc[i][j][e] = 0.f;

#pragma unroll
        for (int ks = 0; ks < 8; ks++) {
            const int k0 = ks * 8;
            unsigned af[2][4];
#pragma unroll
            for (int mi = 0; mi < 2; mi++) {
                const int r = wm + mi * 16 + lr;
                af[mi][0] = __float_as_uint(Qs[r * QS_STR + k0 + lc]);
                af[mi][1] = __float_as_uint(Qs[(r + 8) * QS_STR + k0 + lc]);
                af[mi][2] = __float_as_uint(Qs[r * QS_STR + k0 + 4 + lc]);
                af[mi][3] = __float_as_uint(Qs[(r + 8) * QS_STR + k0 + 4 + lc]);
            }
            unsigned bf[4][2];
#pragma unroll
            for (int ni = 0; ni < 4; ni++) {
                const int r = ni * 8 + lr;
                bf[ni][0] = __float_as_uint(Ksp[r * KS_STR + k0 + lc]);
                bf[ni][1] = __float_as_uint(Ksp[r * KS_STR + k0 + 4 + lc]);
            }
#pragma unroll
            for (int mi = 0; mi < 2; mi++)
#pragma unroll
                for (int ni = 0; ni < 4; ni++)
                    mma8(sacc[mi][ni][0], sacc[mi][ni][1], sacc[mi][ni][2], sacc[mi][ni][3],
                         af[mi][0], af[mi][1], af[mi][2], af[mi][3],
                         bf[ni][0], bf[ni][1]);
        }

        // relu + rowsum + stage P (per-warp region)
#pragma unroll
        for (int mi = 0; mi < 2; mi++)
#pragma unroll
            for (int ni = 0; ni < 4; ni++) {
                float p0 = fmaxf(sacc[mi][ni][0], 0.f);
                float p1 = fmaxf(sacc[mi][ni][1], 0.f);
                float p2 = fmaxf(sacc[mi][ni][2], 0.f);
                float p3 = fmaxf(sacc[mi][ni][3], 0.f);
                rs[mi][0] += p0 + p1;
                rs[mi][1] += p2 + p3;
                const int rb = mi * 16 + lr;
                const int cb = ni * 8 + (lc << 1);
                *reinterpret_cast<float2*>(Pw + rb * PS_STR + cb)       = make_float2(f2tf(p0), f2tf(p1));
                *reinterpret_cast<float2*>(Pw + (rb + 8) * PS_STR + cb) = make_float2(f2tf(p2), f2tf(p3));
            }
        __syncwarp();

        // ctx += P @ V
#pragma unroll
        for (int ks = 0; ks < 4; ks++) {
            const int k0 = ks * 8;
            unsigned af[2][4];
#pragma unroll
            for (int mi = 0; mi < 2; mi++) {
                const int r = mi * 16 + lr;
                af[mi][0] = __float_as_uint(Pw[r * PS_STR + k0 + lc]);
                af[mi][1] = __float_as_uint(Pw[(r + 8) * PS_STR + k0 + lc]);
                af[mi][2] = __float_as_uint(Pw[r * PS_STR + k0 + 4 + lc]);
                af[mi][3] = __float_as_uint(Pw[(r + 8) * PS_STR + k0 + 4 + lc]);
            }
            unsigned bf[8][2];
#pragma unroll
            for (int ni = 0; ni < 8; ni++) {
                bf[ni][0] = __float_as_uint(Vsp[(k0 + lc) * VS_STR + ni * 8 + lr]);
                bf[ni][1] = __float_as_uint(Vsp[(k0 + 4 + lc) * VS_STR + ni * 8 + lr]);
            }
#pragma unroll
            for (int mi = 0; mi < 2; mi++)
#pragma unroll
                for (int ni = 0; ni < 8; ni++)
                    mma8(ctx[mi][ni][0], ctx[mi][ni][1], ctx[mi][ni][2], ctx[mi][ni][3],
                         af[mi][0], af[mi][1], af[mi][2], af[mi][3],
                         bf[ni][0], bf[ni][1]);
        }
        __syncthreads();
    }

    // finalize rowsums
    float inv[2][2];
#pragma unroll
    for (int mi = 0; mi < 2; mi++)
#pragma unroll
        for (int hh = 0; hh < 2; hh++) {
            float r = rs[mi][hh];
            r += __shfl_xor_sync(0xffffffffu, r, 1);
            r += __shfl_xor_sync(0xffffffffu, r, 2);
            inv[mi][hh] = 1.f / (r + 1e-6f);
        }

    // write merged ctx [s, h*64 + d] (tf32-rounded: feeds out-proj GEMM)
    const int tb = tbh / NH, h = tbh % NH;
#pragma unroll
    for (int mi = 0; mi < 2; mi++)
#pragma unroll
        for (int ni = 0; ni < 8; ni++)
#pragma unroll
            for (int e = 0; e < 4; e++) {
                const int qrow = qb * 128 + wm + mi * 16 + lr + ((e >> 1) << 3);
                const int s = tb * NSEQ + qrow;
                const int c = h * DHD + ni * 8 + (lc << 1) + (e & 1);
                g_ctx[(size_t)s * DM + c] = f2tf(ctx[mi][ni][e] * inv[mi][e >> 1]);
            }
}

// ---------------------------------------------------------------------------
// Launch
// ---------------------------------------------------------------------------
extern "C" void kernel_launch(void* const* d_in, const int* in_sizes, int n_in,
                              void* d_out, int out_size) {
    const float* x  = (const float*)d_in[0];
    const float* Wq = (const float*)d_in[1];
    const float* bq = (const float*)d_in[2];
    const float* Wk = (const float*)d_in[3];
    const float* bk = (const float*)d_in[4];
    const float* Wv = (const float*)d_in[5];
    const float* bv = (const float*)d_in[6];
    const float* Wo = (const float*)d_in[7];
    const float* bo = (const float*)d_in[8];
    float* out = (float*)d_out;

    (void)in_sizes; (void)n_in; (void)out_size;

    cudaFuncSetAttribute(gemm_qkv_k, cudaFuncAttributeMaxDynamicSharedMemorySize,
                         (int)(GSMEM_F * sizeof(float)));
    cudaFuncSetAttribute(gemm_out_k, cudaFuncAttributeMaxDynamicSharedMemorySize,
                         (int)(GSMEM_F * sizeof(float)));
    cudaFuncSetAttribute(attn_k, cudaFuncAttributeMaxDynamicSharedMemorySize,
                         (int)(ATT_SMEM_F * sizeof(float)));

    // tf32 pre-round
    const int nx4 = (NS * DM) / 4, nw4 = (DM * DM) / 4;
    cvt_k<<<(nx4 + 255) / 256, 256>>>(x, 0, nx4);
    cvt_k<<<(nw4 + 255) / 256, 256>>>(Wq, 1, nw4);
    cvt_k<<<(nw4 + 255) / 256, 256>>>(Wk, 2, nw4);
    cvt_k<<<(nw4 + 255) / 256, 256>>>(Wv, 3, nw4);
    cvt_k<<<(nw4 + 255) / 256, 256>>>(Wo, 4, nw4);

    // q/k/v projections
    gemm_qkv_k<<<dim3(NS / 128, DM / 128, 3), 256, GSMEM_F * sizeof(float)>>>(bq, bk, bv);

    // spike attention
    attn_k<<<dim3(NSEQ / 128, NTB * NH), 128, ATT_SMEM_F * sizeof(float)>>>();

    // output projection
    gemm_out_k<<<dim3(NS / 128, DM / 128), 256, GSMEM_F * sizeof(float)>>>(bo, out);
}